// round 9
// baseline (speedup 1.0000x reference)
#include <cuda_runtime.h>
#include <cstdint>

#define NN    30000
#define RR    8
#define KD    256
#define HIDD  256
#define ZDIM  128
#define NBASE 30
#define NSEG  (NN*RR)
#define EE    480000
#define K1    (RR*KD + KD)     // 2304  GEMM1 K (agg | x)
#define NRC   (RR*KD)          // 2048  agg columns
#define NW2   (RR*ZDIM + ZDIM) // 1152  GEMM2 N (rel blocks | root)
#define NR2   (RR*ZDIM)        // 1024

// ---- static scratch ----
__device__ float g_agg[(size_t)NSEG * KD];   // 245 MB aggregated inputs (layer1)
__device__ float g_Y[(size_t)NN * NR2];      // 122 MB layer-2 transformed features
__device__ float g_z[(size_t)NN * HIDD];
__device__ float g_xr[(size_t)NN * KD];
__device__ float g_W1[K1 * HIDD];            // [2304, 256] rel-major rows
__device__ float g_W2[KD * NW2];             // [256, 1152]
__device__ int   g_histS[NSEG];
__device__ int   g_histD[NN];
__device__ int   g_offS[NSEG + 1];
__device__ int   g_offD[NN + 1];
__device__ int   g_curS[NSEG];
__device__ int   g_curD[NN];
__device__ int   g_eS1[EE];                  // src per edge (seg-sorted)
__device__ int   g_epk[EE];                  // (src<<3)|rel (dst-sorted)
__device__ float g_esc[EE];                  // 1/cnt(dst,rel)

__device__ __forceinline__ unsigned f2tf32(float f)
{
    unsigned u;
    asm("cvt.rna.tf32.f32 %0, %1;" : "=r"(u) : "f"(f));
    return u;
}
__device__ __forceinline__ float rtf32(float f) { return __uint_as_float(f2tf32(f)); }

// ---------------------------------------------------------------------------
// W1: rows = [r*256+i] rel-stacked then root; cols = 256 outputs. tf32-rounded.
// ---------------------------------------------------------------------------
__global__ void build_w1_kernel(const float* __restrict__ bases,
                                const float* __restrict__ comp,
                                const float* __restrict__ root,
                                float* __restrict__ W)
{
    int idx = blockIdx.x * blockDim.x + threadIdx.x;
    if (idx >= K1 * HIDD) return;
    int row = idx / HIDD;
    int o = idx - row * HIDD;
    float s;
    if (row < NRC) {
        int r = row >> 8;          // row / 256
        int i = row & 255;
        s = 0.f;
#pragma unroll
        for (int b = 0; b < NBASE; b++)
            s += comp[r * NBASE + b] * bases[((size_t)b * KD + i) * HIDD + o];
    } else {
        s = root[(size_t)(row - NRC) * HIDD + o];
    }
    W[idx] = rtf32(s);
}

// W2: rows = input dim k, cols = [r*128+o | root cols]. tf32-rounded.
__global__ void build_w2_kernel(const float* __restrict__ bases,
                                const float* __restrict__ comp,
                                const float* __restrict__ root,
                                float* __restrict__ W)
{
    int idx = blockIdx.x * blockDim.x + threadIdx.x;
    if (idx >= KD * NW2) return;
    int i = idx / NW2;
    int col = idx - i * NW2;
    int r = col / ZDIM;
    int o = col - r * ZDIM;
    float s;
    if (r < RR) {
        s = 0.f;
#pragma unroll
        for (int b = 0; b < NBASE; b++)
            s += comp[r * NBASE + b] * bases[((size_t)b * KD + i) * ZDIM + o];
    } else {
        s = root[(size_t)i * ZDIM + o];
    }
    W[idx] = rtf32(s);
}

__global__ void round_x_kernel(const float* __restrict__ x, float* __restrict__ xr)
{
    int idx = blockIdx.x * blockDim.x + threadIdx.x;
    if (idx >= NN * KD / 4) return;
    float4 v = ((const float4*)x)[idx];
    v.x = rtf32(v.x); v.y = rtf32(v.y); v.z = rtf32(v.z); v.w = rtf32(v.w);
    ((float4*)xr)[idx] = v;
}

// ---------------------------------------------------------------------------
// Topology
// ---------------------------------------------------------------------------
__global__ void zero_topo_kernel(int* __restrict__ hs, int* __restrict__ hd)
{
    int i = blockIdx.x * blockDim.x + threadIdx.x;
    if (i < NSEG) hs[i] = 0;
    if (i < NN) hd[i] = 0;
}

__global__ void count_kernel(const int* __restrict__ dst,
                             const int* __restrict__ et,
                             int* __restrict__ hs, int* __restrict__ hd)
{
    int e = blockIdx.x * blockDim.x + threadIdx.x;
    if (e >= EE) return;
    int d = dst[e];
    atomicAdd(&hs[d * RR + et[e]], 1);
    atomicAdd(&hd[d], 1);
}

// generic single-block exclusive scan: h[n] -> off[n+1], cur[n]
__global__ void __launch_bounds__(1024) scan_kernel(const int* __restrict__ h,
                                                    int* __restrict__ off,
                                                    int* __restrict__ cur, int n)
{
    __shared__ int part[1024];
    int tid = threadIdx.x;
    int chunk = (n + 1023) >> 10;
    int base = tid * chunk;
    int s = 0;
    for (int j = 0; j < chunk; j++) {
        int idx = base + j;
        if (idx < n) s += h[idx];
    }
    part[tid] = s;
    __syncthreads();
    for (int d = 1; d < 1024; d <<= 1) {
        int v = 0;
        if (tid >= d) v = part[tid - d];
        __syncthreads();
        if (tid >= d) part[tid] += v;
        __syncthreads();
    }
    int run = (tid > 0) ? part[tid - 1] : 0;
    for (int j = 0; j < chunk; j++) {
        int idx = base + j;
        if (idx < n) { off[idx] = run; cur[idx] = run; run += h[idx]; }
    }
    if (tid == 1023) off[n] = part[1023];
}

__global__ void permute_kernel(const int* __restrict__ src,
                               const int* __restrict__ dst,
                               const int* __restrict__ et,
                               const int* __restrict__ hs,
                               int* __restrict__ curS, int* __restrict__ curD,
                               int* __restrict__ eS1,
                               int* __restrict__ epk, float* __restrict__ esc)
{
    int e = blockIdx.x * blockDim.x + threadIdx.x;
    if (e >= EE) return;
    int s = src[e], d = dst[e], t = et[e];
    int seg = d * RR + t;
    int p1 = atomicAdd(&curS[seg], 1);
    eS1[p1] = s;
    int p2 = atomicAdd(&curD[d], 1);
    epk[p2] = (s << 3) | t;
    esc[p2] = 1.0f / (float)max(hs[seg], 1);
}

// ---------------------------------------------------------------------------
// Layer-1 segment aggregation: warp owns seg=(dst,rel); mean of x[src] rows.
// x is 30 MB -> L2-resident gathers. tf32 round folded into store.
// ---------------------------------------------------------------------------
__global__ void __launch_bounds__(256)
scatter_seg_kernel(const float* __restrict__ x,
                   const int* __restrict__ eS1,
                   const int* __restrict__ offS,
                   float* __restrict__ agg)
{
    int w = (blockIdx.x * blockDim.x + threadIdx.x) >> 5;
    if (w >= NSEG) return;
    int lane = threadIdx.x & 31;
    int beg = offS[w], end = offS[w + 1];

    float4 a0 = make_float4(0.f, 0.f, 0.f, 0.f);
    float4 a1 = make_float4(0.f, 0.f, 0.f, 0.f);
    for (int e = beg; e < end; e++) {
        const float4* xr4 = (const float4*)(x + (size_t)eS1[e] * KD);
        float4 v0 = xr4[lane];
        float4 v1 = xr4[lane + 32];
        a0.x += v0.x; a0.y += v0.y; a0.z += v0.z; a0.w += v0.w;
        a1.x += v1.x; a1.y += v1.y; a1.z += v1.z; a1.w += v1.w;
    }
    float sc = 1.0f / (float)max(end - beg, 1);
    float4* o4 = (float4*)(agg + (size_t)w * KD);
    a0.x = rtf32(a0.x * sc); a0.y = rtf32(a0.y * sc);
    a0.z = rtf32(a0.z * sc); a0.w = rtf32(a0.w * sc);
    a1.x = rtf32(a1.x * sc); a1.y = rtf32(a1.y * sc);
    a1.z = rtf32(a1.z * sc); a1.w = rtf32(a1.w * sc);
    o4[lane] = a0;
    o4[lane + 32] = a1;
}

// ---------------------------------------------------------------------------
// GEMM core bits
// ---------------------------------------------------------------------------
#define AS_STRIDE 36
#define BS_STRIDE 136
#define AS_WORDS  (128*AS_STRIDE)
#define BS_WORDS  (32*BS_STRIDE)
#define SMEM_BYTES ((2*AS_WORDS + 2*BS_WORDS)*4)

__device__ __forceinline__ void cp16(uint32_t saddr, const void* g, bool pred)
{
    int sz = pred ? 16 : 0;
    asm volatile("cp.async.cg.shared.global [%0], [%1], 16, %2;"
                 :: "r"(saddr), "l"(g), "r"(sz));
}

__device__ __forceinline__ void mma_tf32(float c[4], const unsigned a[4], const unsigned b[2])
{
    asm volatile("mma.sync.aligned.m16n8k8.row.col.f32.tf32.tf32.f32 "
                 "{%0,%1,%2,%3}, {%4,%5,%6,%7}, {%8,%9}, {%0,%1,%2,%3};"
                 : "+f"(c[0]), "+f"(c[1]), "+f"(c[2]), "+f"(c[3])
                 : "r"(a[0]), "r"(a[1]), "r"(a[2]), "r"(a[3]),
                   "r"(b[0]), "r"(b[1]));
}

// ---------------------------------------------------------------------------
// GEMM1: z[M,256] = [agg | xr] @ W1 + bias1, leaky+round fused.
// A split: k<NRC from agg (stride 2048), else xr (stride 256).
// grid: (N/128=2, ceil(M/128)); bn = bx*128, bm = by*128.
// ---------------------------------------------------------------------------
__global__ void __launch_bounds__(256)
gemm1_kernel(const float* __restrict__ agg, const float* __restrict__ xr,
             const float* __restrict__ W, const float* __restrict__ bias,
             float* __restrict__ z, int M)
{
    extern __shared__ float sm[];
    const uint32_t smb = (uint32_t)__cvta_generic_to_shared(sm);

    const int tid   = threadIdx.x;
    const int lane  = tid & 31;
    const int warp  = tid >> 5;
    const int warpM = warp >> 1;
    const int warpN = warp & 1;
    const int gid   = lane >> 2;
    const int tig   = lane & 3;
    const int bn    = blockIdx.x * 128;
    const int bm    = blockIdx.y * 128;

    float acc[2][8][4];
#pragma unroll
    for (int mt = 0; mt < 2; mt++)
#pragma unroll
        for (int nt = 0; nt < 8; nt++)
#pragma unroll
            for (int q = 0; q < 4; q++) acc[mt][nt][q] = 0.f;

    auto loadA = [&](int stage, int k0) {
        uint32_t base = smb + (uint32_t)(stage * AS_WORDS) * 4;
        const float* Ab; int stride, kc0;
        if (k0 < NRC) { Ab = agg; stride = NRC; kc0 = k0; }
        else          { Ab = xr;  stride = KD;  kc0 = k0 - NRC; }
#pragma unroll
        for (int i = 0; i < 4; i++) {
            int c = tid + 256 * i;
            int row = c >> 3, kc = c & 7;
            int gm = bm + row;
            const float* g = Ab + (size_t)gm * stride + kc0 + kc * 4;
            cp16(base + (uint32_t)(row * AS_STRIDE + kc * 4) * 4, g, gm < M);
        }
    };
    auto loadB = [&](int stage, int k0) {
        uint32_t base = smb + (uint32_t)(2 * AS_WORDS + stage * BS_WORDS) * 4;
#pragma unroll
        for (int i = 0; i < 4; i++) {
            int c = tid + 256 * i;
            int kr = c >> 5, nc = c & 31;
            const float* g = W + (size_t)(k0 + kr) * HIDD + bn + nc * 4;
            cp16(base + (uint32_t)(kr * BS_STRIDE + nc * 4) * 4, g, true);
        }
    };

    loadA(0, 0); loadB(0, 0);
    asm volatile("cp.async.commit_group;");

    const int KT = K1 / 32;    // 72
    for (int kt = 0; kt < KT; kt++) {
        int cur = kt & 1;
        if (kt + 1 < KT) {
            loadA(cur ^ 1, (kt + 1) * 32);
            loadB(cur ^ 1, (kt + 1) * 32);
            asm volatile("cp.async.commit_group;");
            asm volatile("cp.async.wait_group 1;");
        } else {
            asm volatile("cp.async.wait_group 0;");
        }
        __syncthreads();

        const unsigned* Au = (const unsigned*)(sm + cur * AS_WORDS);
        const unsigned* Bu = (const unsigned*)(sm + 2 * AS_WORDS + cur * BS_WORDS);

#pragma unroll
        for (int ks = 0; ks < 4; ks++) {
            const int kb = ks * 8;
            unsigned af[2][4];
#pragma unroll
            for (int mt = 0; mt < 2; mt++) {
                int mrow = warpM * 32 + mt * 16;
                af[mt][0] = Au[(mrow + gid) * AS_STRIDE + kb + tig];
                af[mt][1] = Au[(mrow + gid + 8) * AS_STRIDE + kb + tig];
                af[mt][2] = Au[(mrow + gid) * AS_STRIDE + kb + tig + 4];
                af[mt][3] = Au[(mrow + gid + 8) * AS_STRIDE + kb + tig + 4];
            }
#pragma unroll
            for (int nt = 0; nt < 8; nt++) {
                int ncol = warpN * 64 + nt * 8;
                unsigned bf[2];
                bf[0] = Bu[(kb + tig) * BS_STRIDE + ncol + gid];
                bf[1] = Bu[(kb + tig + 4) * BS_STRIDE + ncol + gid];
                mma_tf32(acc[0][nt], af[0], bf);
                mma_tf32(acc[1][nt], af[1], bf);
            }
        }
        __syncthreads();
    }

#pragma unroll
    for (int mt = 0; mt < 2; mt++) {
#pragma unroll
        for (int nt = 0; nt < 8; nt++) {
            int r0 = bm + warpM * 32 + mt * 16 + gid;
            int r1 = r0 + 8;
            int c  = bn + warpN * 64 + nt * 8 + tig * 2;
            float bx = bias[c], by = bias[c + 1];
            if (r0 < M) {
                float vx = acc[mt][nt][0] + bx, vy = acc[mt][nt][1] + by;
                vx = rtf32(vx > 0.f ? vx : 0.01f * vx);
                vy = rtf32(vy > 0.f ? vy : 0.01f * vy);
                *(float2*)(z + (size_t)r0 * HIDD + c) = make_float2(vx, vy);
            }
            if (r1 < M) {
                float vx = acc[mt][nt][2] + bx, vy = acc[mt][nt][3] + by;
                vx = rtf32(vx > 0.f ? vx : 0.01f * vx);
                vy = rtf32(vy > 0.f ? vy : 0.01f * vy);
                *(float2*)(z + (size_t)r1 * HIDD + c) = make_float2(vx, vy);
            }
        }
    }
}

// ---------------------------------------------------------------------------
// GEMM2: Y2/d_out = z @ W2, split epilogue (rel cols -> Yr, root -> dest+bias)
// grid: (NW2/128=9, ceil(M/128))
// ---------------------------------------------------------------------------
__global__ void __launch_bounds__(256)
gemm2_kernel(const float* __restrict__ A, const float* __restrict__ W,
             float* __restrict__ Yr, float* __restrict__ dest,
             const float* __restrict__ bias, int M)
{
    extern __shared__ float sm[];
    const uint32_t smb = (uint32_t)__cvta_generic_to_shared(sm);

    const int tid   = threadIdx.x;
    const int lane  = tid & 31;
    const int warp  = tid >> 5;
    const int warpM = warp >> 1;
    const int warpN = warp & 1;
    const int gid   = lane >> 2;
    const int tig   = lane & 3;
    const int bn    = blockIdx.x * 128;
    const int bm    = blockIdx.y * 128;

    float acc[2][8][4];
#pragma unroll
    for (int mt = 0; mt < 2; mt++)
#pragma unroll
        for (int nt = 0; nt < 8; nt++)
#pragma unroll
            for (int q = 0; q < 4; q++) acc[mt][nt][q] = 0.f;

    auto loadA = [&](int stage, int k0) {
        uint32_t base = smb + (uint32_t)(stage * AS_WORDS) * 4;
#pragma unroll
        for (int i = 0; i < 4; i++) {
            int c = tid + 256 * i;
            int row = c >> 3, kc = c & 7;
            int gm = bm + row;
            const float* g = A + (size_t)gm * KD + k0 + kc * 4;
            cp16(base + (uint32_t)(row * AS_STRIDE + kc * 4) * 4, g, gm < M);
        }
    };
    auto loadB = [&](int stage, int k0) {
        uint32_t base = smb + (uint32_t)(2 * AS_WORDS + stage * BS_WORDS) * 4;
#pragma unroll
        for (int i = 0; i < 4; i++) {
            int c = tid + 256 * i;
            int kr = c >> 5, nc = c & 31;
            const float* g = W + (size_t)(k0 + kr) * NW2 + bn + nc * 4;
            cp16(base + (uint32_t)(kr * BS_STRIDE + nc * 4) * 4, g, true);
        }
    };

    loadA(0, 0); loadB(0, 0);
    asm volatile("cp.async.commit_group;");

    const int KT = KD / 32;    // 8
    for (int kt = 0; kt < KT; kt++) {
        int cur = kt & 1;
        if (kt + 1 < KT) {
            loadA(cur ^ 1, (kt + 1) * 32);
            loadB(cur ^ 1, (kt + 1) * 32);
            asm volatile("cp.async.commit_group;");
            asm volatile("cp.async.wait_group 1;");
        } else {
            asm volatile("cp.async.wait_group 0;");
        }
        __syncthreads();

        const unsigned* Au = (const unsigned*)(sm + cur * AS_WORDS);
        const unsigned* Bu = (const unsigned*)(sm + 2 * AS_WORDS + cur * BS_WORDS);

#pragma unroll
        for (int ks = 0; ks < 4; ks++) {
            const int kb = ks * 8;
            unsigned af[2][4];
#pragma unroll
            for (int mt = 0; mt < 2; mt++) {
                int mrow = warpM * 32 + mt * 16;
                af[mt][0] = Au[(mrow + gid) * AS_STRIDE + kb + tig];
                af[mt][1] = Au[(mrow + gid + 8) * AS_STRIDE + kb + tig];
                af[mt][2] = Au[(mrow + gid) * AS_STRIDE + kb + tig + 4];
                af[mt][3] = Au[(mrow + gid + 8) * AS_STRIDE + kb + tig + 4];
            }
#pragma unroll
            for (int nt = 0; nt < 8; nt++) {
                int ncol = warpN * 64 + nt * 8;
                unsigned bf[2];
                bf[0] = Bu[(kb + tig) * BS_STRIDE + ncol + gid];
                bf[1] = Bu[(kb + tig + 4) * BS_STRIDE + ncol + gid];
                mma_tf32(acc[0][nt], af[0], bf);
                mma_tf32(acc[1][nt], af[1], bf);
            }
        }
        __syncthreads();
    }

#pragma unroll
    for (int mt = 0; mt < 2; mt++) {
#pragma unroll
        for (int nt = 0; nt < 8; nt++) {
            int r0 = bm + warpM * 32 + mt * 16 + gid;
            int r1 = r0 + 8;
            int c  = bn + warpN * 64 + nt * 8 + tig * 2;
            if (c < NR2) {
                if (r0 < M) *(float2*)(Yr + (size_t)r0 * NR2 + c) =
                    make_float2(acc[mt][nt][0], acc[mt][nt][1]);
                if (r1 < M) *(float2*)(Yr + (size_t)r1 * NR2 + c) =
                    make_float2(acc[mt][nt][2], acc[mt][nt][3]);
            } else {
                int cc = c - NR2;
                float bx = bias[cc], by = bias[cc + 1];
                if (r0 < M) *(float2*)(dest + (size_t)r0 * ZDIM + cc) =
                    make_float2(acc[mt][nt][0] + bx, acc[mt][nt][1] + by);
                if (r1 < M) *(float2*)(dest + (size_t)r1 * ZDIM + cc) =
                    make_float2(acc[mt][nt][2] + bx, acc[mt][nt][3] + by);
            }
        }
    }
}

// ---------------------------------------------------------------------------
// Layer-2 dst-owned scatter (OUT=128): out[dst] += esc * Y2[src, rel]
// ---------------------------------------------------------------------------
__global__ void __launch_bounds__(256)
scatter_dst_kernel(const float* __restrict__ Yr,
                   const int* __restrict__ epk,
                   const float* __restrict__ esc,
                   const int* __restrict__ offD,
                   float* __restrict__ out)
{
    int w = (blockIdx.x * blockDim.x + threadIdx.x) >> 5;
    if (w >= NN) return;
    int lane = threadIdx.x & 31;
    int beg = offD[w], end = offD[w + 1];

    float4 acc = make_float4(0.f, 0.f, 0.f, 0.f);
    for (int e = beg; e < end; e++) {
        int pk = epk[e];
        float sc = esc[e];
        const float4* yr = (const float4*)(Yr + (size_t)(pk >> 3) * NR2 + (pk & 7) * ZDIM);
        float4 v = yr[lane];
        acc.x += sc * v.x; acc.y += sc * v.y;
        acc.z += sc * v.z; acc.w += sc * v.w;
    }

    float4* o4 = (float4*)(out + (size_t)w * ZDIM);
    float4 v = o4[lane];
    v.x += acc.x; v.y += acc.y; v.z += acc.z; v.w += acc.w;
    o4[lane] = v;
}

// ---------------------------------------------------------------------------
extern "C" void kernel_launch(void* const* d_in, const int* in_sizes, int n_in,
                              void* d_out, int out_size)
{
    const float* x      = (const float*)d_in[0];
    const int*   ei     = (const int*)d_in[1];
    const int*   et     = (const int*)d_in[2];
    const float* bases1 = (const float*)d_in[3];
    const float* comp1  = (const float*)d_in[4];
    const float* root1  = (const float*)d_in[5];
    const float* bias1  = (const float*)d_in[6];
    const float* bases2 = (const float*)d_in[7];
    const float* comp2  = (const float*)d_in[8];
    const float* root2  = (const float*)d_in[9];
    const float* bias2  = (const float*)d_in[10];
    const int*   src    = ei;
    const int*   dst    = ei + EE;

    void *p;
    float *agg, *Y, *z, *xr, *W1, *W2, *esc;
    int *histS, *histD, *offS, *offD, *curS, *curD, *eS1, *epk;
    cudaGetSymbolAddress(&p, g_agg);   agg  = (float*)p;
    cudaGetSymbolAddress(&p, g_Y);     Y    = (float*)p;
    cudaGetSymbolAddress(&p, g_z);     z    = (float*)p;
    cudaGetSymbolAddress(&p, g_xr);    xr   = (float*)p;
    cudaGetSymbolAddress(&p, g_W1);    W1   = (float*)p;
    cudaGetSymbolAddress(&p, g_W2);    W2   = (float*)p;
    cudaGetSymbolAddress(&p, g_histS); histS = (int*)p;
    cudaGetSymbolAddress(&p, g_histD); histD = (int*)p;
    cudaGetSymbolAddress(&p, g_offS);  offS = (int*)p;
    cudaGetSymbolAddress(&p, g_offD);  offD = (int*)p;
    cudaGetSymbolAddress(&p, g_curS);  curS = (int*)p;
    cudaGetSymbolAddress(&p, g_curD);  curD = (int*)p;
    cudaGetSymbolAddress(&p, g_eS1);   eS1  = (int*)p;
    cudaGetSymbolAddress(&p, g_epk);   epk  = (int*)p;
    cudaGetSymbolAddress(&p, g_esc);   esc  = (float*)p;

    cudaFuncSetAttribute(gemm1_kernel,
                         cudaFuncAttributeMaxDynamicSharedMemorySize, SMEM_BYTES);
    cudaFuncSetAttribute(gemm2_kernel,
                         cudaFuncAttributeMaxDynamicSharedMemorySize, SMEM_BYTES);

    build_w1_kernel<<<(K1 * HIDD + 255) / 256, 256>>>(bases1, comp1, root1, W1);
    build_w2_kernel<<<(KD * NW2 + 255) / 256, 256>>>(bases2, comp2, root2, W2);
    round_x_kernel<<<(NN * KD / 4 + 255) / 256, 256>>>(x, xr);

    zero_topo_kernel<<<(NSEG + 255) / 256, 256>>>(histS, histD);
    count_kernel<<<(EE + 255) / 256, 256>>>(dst, et, histS, histD);
    scan_kernel<<<1, 1024>>>(histS, offS, curS, NSEG);
    scan_kernel<<<1, 1024>>>(histD, offD, curD, NN);
    permute_kernel<<<(EE + 255) / 256, 256>>>(src, dst, et, histS, curS, curD,
                                              eS1, epk, esc);

    // ---- Layer 1: aggregate-first ----
    scatter_seg_kernel<<<(NSEG * 32 + 255) / 256, 256>>>(x, eS1, offS, agg);
    {
        dim3 g(HIDD / 128, (NN + 127) / 128);     // (2, 235)
        gemm1_kernel<<<g, 256, SMEM_BYTES>>>(agg, xr, W1, bias1, z, NN);
    }

    // ---- Layer 2: transform-first ----
    {
        dim3 g(NW2 / 128, (NN + 127) / 128);      // (9, 235)
        gemm2_kernel<<<g, 256, SMEM_BYTES>>>(z, W2, Y, (float*)d_out, bias2, NN);
    }
    scatter_dst_kernel<<<(NN * 32 + 255) / 256, 256>>>(Y, epk, esc, offD, (float*)d_out);
}

// round 10
// speedup vs baseline: 1.7619x; 1.7619x over previous
#include <cuda_runtime.h>
#include <cstdint>

#define NN    30000
#define RR    8
#define KD    256
#define HIDD  256
#define ZDIM  128
#define NBASE 30
#define NSEG  (NN*RR)
#define EE    480000
#define NW1   (RR*HIDD + HIDD)   // 2304
#define NW2   (RR*ZDIM + ZDIM)   // 1152
#define NR1   (RR*HIDD)          // 2048
#define NR2   (RR*ZDIM)          // 1024

// ---- static scratch ----
__device__ float g_Y[(size_t)NN * NR1];
__device__ float g_z[(size_t)NN * HIDD];
__device__ float g_xr[(size_t)NN * KD];
__device__ float g_W1[KD * NW1];             // [k][n] build layout
__device__ float g_W2[KD * NW2];
__device__ float g_W1t[NW1 * KD];            // [n][k] transposed for ldmatrix B
__device__ float g_W2t[NW2 * KD];
__device__ float g_inv[NSEG];
__device__ int   g_cnt[NSEG];
__device__ int   g_hist[NN];
__device__ int   g_offA[NN + 1];
__device__ int   g_offB[NN];
__device__ int   g_epk[EE];                  // (src<<3)|rel  (dst-sorted)
__device__ float g_esc[EE];                  // 1/cnt(dst,rel)

__device__ __forceinline__ unsigned f2tf32(float f)
{
    unsigned u;
    asm("cvt.rna.tf32.f32 %0, %1;" : "=r"(u) : "f"(f));
    return u;
}
__device__ __forceinline__ float rtf32(float f) { return __uint_as_float(f2tf32(f)); }

// ---------------------------------------------------------------------------
// W build (R7 layout: [k][ncol], rel blocks then root), tf32-rounded.
// ---------------------------------------------------------------------------
__global__ void build_w_kernel(const float* __restrict__ bases,
                               const float* __restrict__ comp,
                               const float* __restrict__ root,
                               float* __restrict__ W, int out)
{
    int idx = blockIdx.x * blockDim.x + threadIdx.x;
    int ncol = (RR + 1) * out;
    int total = KD * ncol;
    if (idx >= total) return;
    int i = idx / ncol;
    int col = idx - i * ncol;
    int r = col / out;
    int o = col - r * out;
    float s;
    if (r < RR) {
        s = 0.f;
#pragma unroll
        for (int b = 0; b < NBASE; b++)
            s += comp[r * NBASE + b] * bases[((size_t)b * KD + i) * out + o];
    } else {
        s = root[(size_t)i * out + o];
    }
    W[idx] = rtf32(s);
}

// 32x32 smem-tile transpose: W[k][n] -> Wt[n][k]
__global__ void transpose_kernel(const float* __restrict__ W, float* __restrict__ Wt,
                                 int K, int N)
{
    __shared__ float t[32][33];
    int k0 = blockIdx.x * 32, n0 = blockIdx.y * 32;
    int tx = threadIdx.x & 31, ty = threadIdx.x >> 5;   // 256 threads, ty 0..7
#pragma unroll
    for (int j = 0; j < 32; j += 8)
        t[ty + j][tx] = W[(size_t)(k0 + ty + j) * N + n0 + tx];
    __syncthreads();
#pragma unroll
    for (int j = 0; j < 32; j += 8)
        Wt[(size_t)(n0 + ty + j) * K + k0 + tx] = t[tx][ty + j];
}

__global__ void round_x_kernel(const float* __restrict__ x, float* __restrict__ xr)
{
    int idx = blockIdx.x * blockDim.x + threadIdx.x;
    if (idx >= NN * KD / 4) return;
    float4 v = ((const float4*)x)[idx];
    v.x = rtf32(v.x); v.y = rtf32(v.y); v.z = rtf32(v.z); v.w = rtf32(v.w);
    ((float4*)xr)[idx] = v;
}

// ---------------------------------------------------------------------------
// Topology (R7)
// ---------------------------------------------------------------------------
__global__ void zero_topo_kernel(int* __restrict__ cnt, int* __restrict__ hist)
{
    int i = blockIdx.x * blockDim.x + threadIdx.x;
    if (i < NSEG) cnt[i] = 0;
    if (i < NN) hist[i] = 0;
}

__global__ void count_kernel(const int* __restrict__ dst,
                             const int* __restrict__ et,
                             int* __restrict__ cnt, int* __restrict__ hist)
{
    int e = blockIdx.x * blockDim.x + threadIdx.x;
    if (e >= EE) return;
    int d = dst[e];
    atomicAdd(&cnt[d * RR + et[e]], 1);
    atomicAdd(&hist[d], 1);
}

__global__ void inv_kernel(const int* __restrict__ cnt, float* __restrict__ inv)
{
    int i = blockIdx.x * blockDim.x + threadIdx.x;
    if (i < NSEG) inv[i] = 1.0f / (float)max(cnt[i], 1);
}

__global__ void __launch_bounds__(1024) scan_kernel(const int* __restrict__ hist,
                                                    int* __restrict__ offA,
                                                    int* __restrict__ offB)
{
    __shared__ int part[1024];
    int tid = threadIdx.x;
    int base = tid * 32;
    int s = 0;
#pragma unroll
    for (int j = 0; j < 32; j++) {
        int idx = base + j;
        if (idx < NN) s += hist[idx];
    }
    part[tid] = s;
    __syncthreads();
    for (int d = 1; d < 1024; d <<= 1) {
        int v = 0;
        if (tid >= d) v = part[tid - d];
        __syncthreads();
        if (tid >= d) part[tid] += v;
        __syncthreads();
    }
    int run = (tid > 0) ? part[tid - 1] : 0;
#pragma unroll
    for (int j = 0; j < 32; j++) {
        int idx = base + j;
        if (idx < NN) { offA[idx] = run; offB[idx] = run; run += hist[idx]; }
    }
    if (tid == 1023) offA[NN] = part[1023];
}

__global__ void permute_kernel(const int* __restrict__ src,
                               const int* __restrict__ dst,
                               const int* __restrict__ et,
                               const float* __restrict__ inv,
                               int* __restrict__ offB,
                               int* __restrict__ epk, float* __restrict__ esc)
{
    int e = blockIdx.x * blockDim.x + threadIdx.x;
    if (e >= EE) return;
    int s = src[e], d = dst[e], t = et[e];
    int pos = atomicAdd(&offB[d], 1);
    epk[pos] = (s << 3) | t;
    esc[pos] = inv[d * RR + t];
}

// ---------------------------------------------------------------------------
// tf32 GEMM with ldmatrix fragment loads.
// A row-major [m][k] in smem, B n-major [n][k] (weights pre-transposed).
// Both tiles: 128 rows x 32 k, stride 32 words, XOR-chunk swizzle
// (16B chunk ch of row r stored at chunk ch^(r&7)) -> conflict-free
// cp.async stores AND ldmatrix reads.
// Block 128x128, 256 thr, warp tile 32x64, m16n8k8 tf32, 2-stage cp.async.
// Split epilogue: cols < NR -> Yr ; cols >= NR -> dest + bias.
// ---------------------------------------------------------------------------
#define TILE_WORDS (128*32)
#define SMEM_BYTES (4*TILE_WORDS*4)     // 2 stages x (A+B) = 65536 B

__device__ __forceinline__ void cp16(uint32_t saddr, const void* g, bool pred)
{
    int sz = pred ? 16 : 0;
    asm volatile("cp.async.cg.shared.global [%0], [%1], 16, %2;"
                 :: "r"(saddr), "l"(g), "r"(sz));
}

__device__ __forceinline__ void ldsm4(unsigned r[4], uint32_t addr)
{
    asm volatile("ldmatrix.sync.aligned.m8n8.x4.shared.b16 {%0,%1,%2,%3}, [%4];"
                 : "=r"(r[0]), "=r"(r[1]), "=r"(r[2]), "=r"(r[3]) : "r"(addr));
}

__device__ __forceinline__ void mma_tf32(float c[4], const unsigned a[4], const unsigned b[2])
{
    asm volatile("mma.sync.aligned.m16n8k8.row.col.f32.tf32.tf32.f32 "
                 "{%0,%1,%2,%3}, {%4,%5,%6,%7}, {%8,%9}, {%0,%1,%2,%3};"
                 : "+f"(c[0]), "+f"(c[1]), "+f"(c[2]), "+f"(c[3])
                 : "r"(a[0]), "r"(a[1]), "r"(a[2]), "r"(a[3]),
                   "r"(b[0]), "r"(b[1]));
}

__global__ void __launch_bounds__(256)
gemm_kernel(const float* __restrict__ A, const float* __restrict__ Wt,
            float* __restrict__ Yr, float* __restrict__ dest,
            const float* __restrict__ bias, int M, int NR, int OUT)
{
    extern __shared__ float sm[];
    const uint32_t smb = (uint32_t)__cvta_generic_to_shared(sm);

    const int tid   = threadIdx.x;
    const int lane  = tid & 31;
    const int warp  = tid >> 5;
    const int warpM = warp >> 1;
    const int warpN = warp & 1;
    const int gid   = lane >> 2;
    const int tig   = lane & 3;
    const int bm    = blockIdx.x * 128;
    const int bn    = blockIdx.y * 128;

    float acc[2][8][4];
#pragma unroll
    for (int mt = 0; mt < 2; mt++)
#pragma unroll
        for (int nt = 0; nt < 8; nt++)
#pragma unroll
            for (int q = 0; q < 4; q++) acc[mt][nt][q] = 0.f;

    // ldmatrix per-lane geometry. All row bases are multiples of 8 plus l7,
    // so row&7 == l7 (constant per thread).
    const int mat = lane >> 3;
    const int l7  = lane & 7;
    // A matrices: 0:(m+0,k+0) 1:(m+8,k+0) 2:(m+0,k+4) 3:(m+8,k+4)
    const int aRow = warpM * 32 + (mat & 1) * 8 + l7;      // + mt*16
    const int aKc  = (mat >> 1);                            // chunk offset 0/1
    // B matrices: 0:(n+0,k+0) 1:(n+0,k+4) 2:(n+8,k+0) 3:(n+8,k+4)
    const int bRow = warpN * 64 + (mat >> 1) * 8 + l7;      // + p*16
    const int bKc  = (mat & 1);

    auto loadA = [&](int stage, int k0) {
        uint32_t base = smb + (uint32_t)(stage * 2 * TILE_WORDS) * 4;
#pragma unroll
        for (int i = 0; i < 4; i++) {
            int c = tid + 256 * i;
            int row = c >> 3, ch = c & 7;
            int gm = bm + row;
            const float* g = A + (size_t)gm * KD + k0 + ch * 4;
            uint32_t sa = base + (uint32_t)row * 128 + (uint32_t)((ch ^ (row & 7)) << 4);
            cp16(sa, g, gm < M);
        }
    };
    auto loadB = [&](int stage, int k0) {
        uint32_t base = smb + (uint32_t)(stage * 2 * TILE_WORDS + TILE_WORDS) * 4;
#pragma unroll
        for (int i = 0; i < 4; i++) {
            int c = tid + 256 * i;
            int row = c >> 3, ch = c & 7;
            const float* g = Wt + (size_t)(bn + row) * KD + k0 + ch * 4;
            uint32_t sa = base + (uint32_t)row * 128 + (uint32_t)((ch ^ (row & 7)) << 4);
            cp16(sa, g, true);
        }
    };

    loadA(0, 0); loadB(0, 0);
    asm volatile("cp.async.commit_group;");

    const int KT = KD / 32;    // 8
    for (int kt = 0; kt < KT; kt++) {
        int cur = kt & 1;
        if (kt + 1 < KT) {
            loadA(cur ^ 1, (kt + 1) * 32);
            loadB(cur ^ 1, (kt + 1) * 32);
            asm volatile("cp.async.commit_group;");
            asm volatile("cp.async.wait_group 1;");
        } else {
            asm volatile("cp.async.wait_group 0;");
        }
        __syncthreads();

        uint32_t aBase = smb + (uint32_t)(cur * 2 * TILE_WORDS) * 4;
        uint32_t bBase = aBase + (uint32_t)TILE_WORDS * 4;

#pragma unroll
        for (int ks = 0; ks < 4; ks++) {
            const int kcL = ks * 2;     // chunk index of this 8-k slice
            unsigned af[2][4];
#pragma unroll
            for (int mt = 0; mt < 2; mt++) {
                int row = aRow + mt * 16;
                uint32_t sa = aBase + (uint32_t)row * 128
                            + (uint32_t)(((kcL + aKc) ^ l7) << 4);
                ldsm4(af[mt], sa);
            }
            unsigned bw[4][4];
#pragma unroll
            for (int p = 0; p < 4; p++) {
                int row = bRow + p * 16;
                uint32_t sa = bBase + (uint32_t)row * 128
                            + (uint32_t)(((kcL + bKc) ^ l7) << 4);
                ldsm4(bw[p], sa);
            }
#pragma unroll
            for (int nt = 0; nt < 8; nt++) {
                const unsigned* bv = (nt & 1) ? &bw[nt >> 1][2] : &bw[nt >> 1][0];
                mma_tf32(acc[0][nt], af[0], bv);
                mma_tf32(acc[1][nt], af[1], bv);
            }
        }
        __syncthreads();
    }

    // split epilogue (R7)
#pragma unroll
    for (int mt = 0; mt < 2; mt++) {
#pragma unroll
        for (int nt = 0; nt < 8; nt++) {
            int r0 = bm + warpM * 32 + mt * 16 + gid;
            int r1 = r0 + 8;
            int c  = bn + warpN * 64 + nt * 8 + tig * 2;
            if (c < NR) {
                if (r0 < M) *(float2*)(Yr + (size_t)r0 * NR + c) =
                    make_float2(acc[mt][nt][0], acc[mt][nt][1]);
                if (r1 < M) *(float2*)(Yr + (size_t)r1 * NR + c) =
                    make_float2(acc[mt][nt][2], acc[mt][nt][3]);
            } else {
                int cc = c - NR;
                float bx = bias[cc], by = bias[cc + 1];
                if (r0 < M) *(float2*)(dest + (size_t)r0 * OUT + cc) =
                    make_float2(acc[mt][nt][0] + bx, acc[mt][nt][1] + by);
                if (r1 < M) *(float2*)(dest + (size_t)r1 * OUT + cc) =
                    make_float2(acc[mt][nt][2] + bx, acc[mt][nt][3] + by);
            }
        }
    }
}

// ---------------------------------------------------------------------------
// dst-owned scatter (R7): warp w owns node w; regs accumulate, one plain RMW.
// ---------------------------------------------------------------------------
template<int OUT, bool LEAKY>
__global__ void __launch_bounds__(256)
scatter_dst_kernel(const float* __restrict__ Yr,
                   const int* __restrict__ epk,
                   const float* __restrict__ esc,
                   const int* __restrict__ offA,
                   float* __restrict__ out)
{
    const int NR = RR * OUT;
    const int IT = OUT / 128;
    int w = (blockIdx.x * blockDim.x + threadIdx.x) >> 5;
    if (w >= NN) return;
    int lane = threadIdx.x & 31;
    int beg = offA[w], end = offA[w + 1];

    float4 acc[IT];
#pragma unroll
    for (int it = 0; it < IT; it++) acc[it] = make_float4(0.f, 0.f, 0.f, 0.f);

    for (int e = beg; e < end; e++) {
        int pk = epk[e];
        float sc = esc[e];
        const float4* yr = (const float4*)(Yr + (size_t)(pk >> 3) * NR + (pk & 7) * OUT);
#pragma unroll
        for (int it = 0; it < IT; it++) {
            float4 v = yr[lane + it * 32];
            acc[it].x += sc * v.x; acc[it].y += sc * v.y;
            acc[it].z += sc * v.z; acc[it].w += sc * v.w;
        }
    }

    float4* o4 = (float4*)(out + (size_t)w * OUT);
#pragma unroll
    for (int it = 0; it < IT; it++) {
        float4 v = o4[lane + it * 32];
        v.x += acc[it].x; v.y += acc[it].y; v.z += acc[it].z; v.w += acc[it].w;
        if (LEAKY) {
            v.x = rtf32(v.x > 0.f ? v.x : 0.01f * v.x);
            v.y = rtf32(v.y > 0.f ? v.y : 0.01f * v.y);
            v.z = rtf32(v.z > 0.f ? v.z : 0.01f * v.z);
            v.w = rtf32(v.w > 0.f ? v.w : 0.01f * v.w);
        }
        o4[lane + it * 32] = v;
    }
}

// ---------------------------------------------------------------------------
extern "C" void kernel_launch(void* const* d_in, const int* in_sizes, int n_in,
                              void* d_out, int out_size)
{
    const float* x      = (const float*)d_in[0];
    const int*   ei     = (const int*)d_in[1];
    const int*   et     = (const int*)d_in[2];
    const float* bases1 = (const float*)d_in[3];
    const float* comp1  = (const float*)d_in[4];
    const float* root1  = (const float*)d_in[5];
    const float* bias1  = (const float*)d_in[6];
    const float* bases2 = (const float*)d_in[7];
    const float* comp2  = (const float*)d_in[8];
    const float* root2  = (const float*)d_in[9];
    const float* bias2  = (const float*)d_in[10];
    const int*   src    = ei;
    const int*   dst    = ei + EE;

    void *p;
    float *Y, *z, *xr, *W1, *W2, *W1t, *W2t, *inv, *esc;
    int *cnt, *hist, *offA, *offB, *epk;
    cudaGetSymbolAddress(&p, g_Y);    Y    = (float*)p;
    cudaGetSymbolAddress(&p, g_z);    z    = (float*)p;
    cudaGetSymbolAddress(&p, g_xr);   xr   = (float*)p;
    cudaGetSymbolAddress(&p, g_W1);   W1   = (float*)p;
    cudaGetSymbolAddress(&p, g_W2);   W2   = (float*)p;
    cudaGetSymbolAddress(&p, g_W1t);  W1t  = (float*)p;
    cudaGetSymbolAddress(&p, g_W2t);  W2t  = (float*)p;
    cudaGetSymbolAddress(&p, g_inv);  inv  = (float*)p;
    cudaGetSymbolAddress(&p, g_cnt);  cnt  = (int*)p;
    cudaGetSymbolAddress(&p, g_hist); hist = (int*)p;
    cudaGetSymbolAddress(&p, g_offA); offA = (int*)p;
    cudaGetSymbolAddress(&p, g_offB); offB = (int*)p;
    cudaGetSymbolAddress(&p, g_epk);  epk  = (int*)p;
    cudaGetSymbolAddress(&p, g_esc);  esc  = (float*)p;

    cudaFuncSetAttribute(gemm_kernel,
                         cudaFuncAttributeMaxDynamicSharedMemorySize, SMEM_BYTES);

    // weights: build [k][n], transpose to [n][k]
    build_w_kernel<<<(KD * NW1 + 255) / 256, 256>>>(bases1, comp1, root1, W1, HIDD);
    build_w_kernel<<<(KD * NW2 + 255) / 256, 256>>>(bases2, comp2, root2, W2, ZDIM);
    {
        dim3 g1(KD / 32, NW1 / 32);
        transpose_kernel<<<g1, 256>>>(W1, W1t, KD, NW1);
        dim3 g2(KD / 32, NW2 / 32);
        transpose_kernel<<<g2, 256>>>(W2, W2t, KD, NW2);
    }
    round_x_kernel<<<(NN * KD / 4 + 255) / 256, 256>>>(x, xr);

    // topology
    zero_topo_kernel<<<(NSEG + 255) / 256, 256>>>(cnt, hist);
    count_kernel<<<(EE + 255) / 256, 256>>>(dst, et, cnt, hist);
    inv_kernel<<<(NSEG + 255) / 256, 256>>>(cnt, inv);
    scan_kernel<<<1, 1024>>>(hist, offA, offB);
    permute_kernel<<<(EE + 255) / 256, 256>>>(src, dst, et, inv, offB, epk, esc);

    const int scatBlocks = (NN * 32 + 255) / 256;

    // ---- Layer 1 (transform-first) ----
    {
        dim3 g((NN + 127) / 128, NW1 / 128);
        gemm_kernel<<<g, 256, SMEM_BYTES>>>(xr, W1t, Y, z, bias1, NN, NR1, HIDD);
    }
    scatter_dst_kernel<HIDD, true><<<scatBlocks, 256>>>(Y, epk, esc, offA, z);

    // ---- Layer 2 (transform-first) ----
    {
        dim3 g((NN + 127) / 128, NW2 / 128);
        gemm_kernel<<<g, 256, SMEM_BYTES>>>(z, W2t, Y, (float*)d_out, bias2, NN, NR2, ZDIM);
    }
    scatter_dst_kernel<ZDIM, false><<<scatBlocks, 256>>>(Y, epk, esc, offA, (float*)d_out);
}